// round 8
// baseline (speedup 1.0000x reference)
#include <cuda_runtime.h>
#include <math.h>
#include <stdint.h>

#define TOKENS 8192
#define DM 1024
#define DF 2048
#define NE 8

// ---------------- scratch (device globals: allocation-free, graph-safe) -------------
__device__ int   g_cnt[2];
__device__ int   g_idx[2][TOKENS];
__device__ float g_scale[2][TOKENS];
__device__ float g_h[2][(size_t)TOKENS * DF];

__global__ void reset_kernel() {
    if (threadIdx.x < 2) g_cnt[threadIdx.x] = 0;
}

// One warp per token: logits -> softmax -> top-2 -> compact active tokens (fp32, exact).
__global__ __launch_bounds__(256) void gate_kernel(const float* __restrict__ x,
                                                   const float* __restrict__ gw,
                                                   const float* __restrict__ gb) {
    __shared__ float sgw[DM * NE];
    for (int i = threadIdx.x; i < DM * NE; i += 256) sgw[i] = gw[i];
    __syncthreads();

    const int t    = (int)((blockIdx.x * 256u + threadIdx.x) >> 5);
    const int lane = threadIdx.x & 31;
    if (t >= TOKENS) return;

    const float4* xr = (const float4*)(x + (size_t)t * DM);
    float acc[NE];
#pragma unroll
    for (int e = 0; e < NE; e++) acc[e] = 0.f;
    for (int d4 = lane; d4 < DM / 4; d4 += 32) {
        float4 xv = xr[d4];
        const float xs[4] = {xv.x, xv.y, xv.z, xv.w};
#pragma unroll
        for (int q = 0; q < 4; q++) {
            const float4* wp = (const float4*)(sgw + (d4 * 4 + q) * NE);
            float4 w0 = wp[0], w1 = wp[1];
            acc[0] += xs[q] * w0.x; acc[1] += xs[q] * w0.y;
            acc[2] += xs[q] * w0.z; acc[3] += xs[q] * w0.w;
            acc[4] += xs[q] * w1.x; acc[5] += xs[q] * w1.y;
            acc[6] += xs[q] * w1.z; acc[7] += xs[q] * w1.w;
        }
    }
#pragma unroll
    for (int e = 0; e < NE; e++)
#pragma unroll
        for (int o = 16; o > 0; o >>= 1) acc[e] += __shfl_xor_sync(0xffffffffu, acc[e], o);

    if (lane == 0) {
        float p[NE];
        float mx = -1e30f;
#pragma unroll
        for (int e = 0; e < NE; e++) { p[e] = acc[e] + gb[e]; mx = fmaxf(mx, p[e]); }
        float s = 0.f;
#pragma unroll
        for (int e = 0; e < NE; e++) { p[e] = expf(p[e] - mx); s += p[e]; }
        float inv = 1.f / s;
#pragma unroll
        for (int e = 0; e < NE; e++) p[e] *= inv;
        int i1 = 0;
#pragma unroll
        for (int e = 1; e < NE; e++) if (p[e] > p[i1]) i1 = e;
        int i2 = (i1 == 0) ? 1 : 0;
#pragma unroll
        for (int e = 0; e < NE; e++) if (e != i1 && p[e] > p[i2]) i2 = e;
        if (i1 == 0) { int s0 = atomicAdd(&g_cnt[0], 1); g_idx[0][s0] = t; g_scale[0][s0] = p[0]; }
        if (i2 == 1) { int s1 = atomicAdd(&g_cnt[1], 1); g_idx[1][s1] = t; g_scale[1][s1] = p[1]; }
    }
}

// ---------------- tf32 mma.sync GEMM with cp.async pipeline ----------------
__device__ __forceinline__ float tf32r(float x) {
    float y;
    asm("cvt.rna.tf32.f32 %0, %1;" : "=f"(y) : "f"(x));
    return y;
}
__device__ __forceinline__ void mma_tf32(float* d, const uint32_t* a, const uint32_t* b) {
    asm volatile(
        "mma.sync.aligned.m16n8k8.row.col.f32.tf32.tf32.f32 "
        "{%0,%1,%2,%3}, {%4,%5,%6,%7}, {%8,%9}, {%0,%1,%2,%3};"
        : "+f"(d[0]), "+f"(d[1]), "+f"(d[2]), "+f"(d[3])
        : "r"(a[0]), "r"(a[1]), "r"(a[2]), "r"(a[3]), "r"(b[0]), "r"(b[1]));
}
__device__ __forceinline__ uint32_t smem_u32(const void* p) {
    uint32_t a;
    asm("{ .reg .u64 t; cvta.to.shared.u64 t, %1; cvt.u32.u64 %0, t; }" : "=r"(a) : "l"(p));
    return a;
}
#define CP_ASYNC16(dst, src, srcsz) \
    asm volatile("cp.async.cg.shared.global [%0], [%1], 16, %2;" \
                 :: "r"(dst), "l"(src), "r"(srcsz))
#define CP_COMMIT() asm volatile("cp.async.commit_group;" ::: "memory")
#define CP_WAIT1()  asm volatile("cp.async.wait_group 1;" ::: "memory")

// CTA tile 256x128, BK=32, 16 warps as 4(M) x 4(N); warp tile 64x32. 512 threads.
#define BM 256
#define BN 128
#define BK 32
#define AS_STRIDE 36
#define BS_STRIDE 136
#define STAGES 3
#define AS_FLOATS (BM * AS_STRIDE)
#define STAGE_FLOATS (AS_FLOATS + BK * BS_STRIDE)
#define STAGE_BYTES (STAGE_FLOATS * 4)
#define SMEM_TOTAL (STAGES * STAGE_BYTES)

template <int KSLICE, bool IS_FFN1, int SPLITK>
__global__ void __launch_bounds__(512, 1) ffn_mma_kernel(const float* __restrict__ x,
                                                         const float* __restrict__ W,
                                                         const float* __restrict__ bias,
                                                         float* __restrict__ outp) {
    const int e     = blockIdx.z / SPLITK;
    const int split = blockIdx.z % SPLITK;
    const int n_act = g_cnt[e];
    const int m0    = blockIdx.y * BM;
    if (m0 >= n_act) return;
    const int NOUT  = IS_FFN1 ? DF : DM;
    const int KTOT  = IS_FFN1 ? DM : DF;
    const int n0    = blockIdx.x * BN;
    const int kbase = split * KSLICE;
    const float* __restrict__ Wq = W + (size_t)e * KTOT * NOUT;

    extern __shared__ float dynsmem[];

    const int tid  = threadIdx.x;
    const int wid  = tid >> 5;
    const int lane = tid & 31;
    const int gid  = lane >> 2;
    const int tig  = lane & 3;
    const int wm0  = (wid >> 2) * 64;   // 0 / 64 / 128 / 192
    const int wn0  = (wid & 3) * 32;    // 0 / 32 / 64 / 96

    // A gather: 2 threads per row, 16 floats each
    const int arow = tid >> 1, aseg = tid & 1;
    const float* aptr;
    uint32_t a_sz;
    {
        int r = m0 + arow;
        bool v = r < n_act;
        int ridx = v ? (IS_FFN1 ? g_idx[e][r] : r) : 0;
        aptr = (IS_FFN1 ? (x + (size_t)ridx * DM) : (g_h[e] + (size_t)ridx * DF))
               + kbase + aseg * 16;
        a_sz = v ? 16u : 0u;
    }
    // B: 16 threads per k-row, 8 floats each
    const int bk = tid >> 4, bq = tid & 15;
    const float* bptr = Wq + (size_t)(kbase + bk) * NOUT + n0 + bq * 8;

    const uint32_t as_dst = smem_u32(dynsmem) + (uint32_t)((arow * AS_STRIDE + aseg * 16) * 4);
    const uint32_t bs_dst = smem_u32(dynsmem) +
                            (uint32_t)((AS_FLOATS + bk * BS_STRIDE + bq * 8) * 4);

    const int NCHUNK = KSLICE / BK;

    auto issue = [&](int chunk) {
        if (chunk < NCHUNK) {
            const uint32_t sb = (uint32_t)((chunk % STAGES) * STAGE_BYTES);
            const float* ap = aptr + chunk * BK;
            const float* bp = bptr + (size_t)chunk * BK * NOUT;
#pragma unroll
            for (int i = 0; i < 4; i++)
                CP_ASYNC16(as_dst + sb + i * 16, ap + i * 4, a_sz);
#pragma unroll
            for (int i = 0; i < 2; i++)
                CP_ASYNC16(bs_dst + sb + i * 16, bp + i * 4, 16u);
        }
        CP_COMMIT();   // uniform groups: wait_group(1) always pins chunk i
    };

    float c[4][4][4];
#pragma unroll
    for (int mi = 0; mi < 4; mi++)
#pragma unroll
        for (int ni = 0; ni < 4; ni++)
#pragma unroll
            for (int q = 0; q < 4; q++) c[mi][ni][q] = 0.f;

    issue(0);
    issue(1);

    for (int i = 0; i < NCHUNK; i++) {
        CP_WAIT1();
        __syncthreads();
        // issue next chunk into stage (i+2)%3 — never the stage being read (i%3),
        // and the stage it overwrites ((i-1)%3) was released at this sync.
        issue(i + 2);

        const float* As = dynsmem + (i % STAGES) * STAGE_FLOATS;
        const float* Bs = As + AS_FLOATS;

#pragma unroll
        for (int ks = 0; ks < 4; ks++) {
            const int kk = ks * 8;
            uint32_t a[4][4], b[4][2];
#pragma unroll
            for (int mi = 0; mi < 4; mi++) {
                const int r = wm0 + mi * 16 + gid;
                a[mi][0] = __float_as_uint(tf32r(As[r * AS_STRIDE + kk + tig]));
                a[mi][1] = __float_as_uint(tf32r(As[(r + 8) * AS_STRIDE + kk + tig]));
                a[mi][2] = __float_as_uint(tf32r(As[r * AS_STRIDE + kk + tig + 4]));
                a[mi][3] = __float_as_uint(tf32r(As[(r + 8) * AS_STRIDE + kk + tig + 4]));
            }
#pragma unroll
            for (int ni = 0; ni < 4; ni++) {
                const int nn = wn0 + ni * 8 + gid;
                b[ni][0] = __float_as_uint(tf32r(Bs[(kk + tig) * BS_STRIDE + nn]));
                b[ni][1] = __float_as_uint(tf32r(Bs[(kk + tig + 4) * BS_STRIDE + nn]));
            }
#pragma unroll
            for (int mi = 0; mi < 4; mi++)
#pragma unroll
                for (int ni = 0; ni < 4; ni++) mma_tf32(c[mi][ni], a[mi], b[ni]);
        }
    }

    // ---------------- epilogue ----------------
    const float* bb = bias + (size_t)e * NOUT + n0;
    if (IS_FFN1) {
#pragma unroll
        for (int mi = 0; mi < 4; mi++) {
#pragma unroll
            for (int half = 0; half < 2; half++) {
                const int r = m0 + wm0 + mi * 16 + gid + half * 8;
                if (r < n_act) {
                    float* hrow = g_h[e] + (size_t)r * DF + n0;
#pragma unroll
                    for (int ni = 0; ni < 4; ni++) {
                        const int nn = wn0 + ni * 8 + 2 * tig;
                        float v0 = c[mi][ni][2 * half + 0] + bb[nn];
                        float v1 = c[mi][ni][2 * half + 1] + bb[nn + 1];
                        float2 o;
                        o.x = 0.5f * v0 * (1.f + erff(v0 * 0.70710678118654752f));
                        o.y = 0.5f * v1 * (1.f + erff(v1 * 0.70710678118654752f));
                        *(float2*)(hrow + nn) = o;
                    }
                }
            }
        }
    } else {
#pragma unroll
        for (int mi = 0; mi < 4; mi++) {
#pragma unroll
            for (int half = 0; half < 2; half++) {
                const int r = m0 + wm0 + mi * 16 + gid + half * 8;
                if (r < n_act) {
                    const int   tok = g_idx[e][r];
                    const float sc  = g_scale[e][r];
                    float* orow = outp + (size_t)tok * DM + n0;
#pragma unroll
                    for (int ni = 0; ni < 4; ni++) {
                        const int nn = wn0 + ni * 8 + 2 * tig;
                        float bb0 = (split == 0) ? bb[nn]     : 0.f;  // bias added once
                        float bb1 = (split == 0) ? bb[nn + 1] : 0.f;
                        atomicAdd(orow + nn,     sc * (c[mi][ni][2 * half + 0] + bb0));
                        atomicAdd(orow + nn + 1, sc * (c[mi][ni][2 * half + 1] + bb1));
                    }
                }
            }
        }
    }
}

extern "C" void kernel_launch(void* const* d_in, const int* in_sizes, int n_in,
                              void* d_out, int out_size) {
    const float* x  = (const float*)d_in[0];
    const float* gw = (const float*)d_in[1];
    const float* gb = (const float*)d_in[2];
    const float* w1 = (const float*)d_in[3];
    const float* b1 = (const float*)d_in[4];
    const float* w2 = (const float*)d_in[5];
    const float* b2 = (const float*)d_in[6];
    float* out = (float*)d_out;

    cudaFuncSetAttribute(ffn_mma_kernel<DM, true, 1>,
                         cudaFuncAttributeMaxDynamicSharedMemorySize, SMEM_TOTAL);
    cudaFuncSetAttribute(ffn_mma_kernel<DF / 2, false, 2>,
                         cudaFuncAttributeMaxDynamicSharedMemorySize, SMEM_TOTAL);

    cudaMemsetAsync(out, 0, (size_t)out_size * sizeof(float), 0);
    reset_kernel<<<1, 32>>>();
    gate_kernel<<<TOKENS / 8, 256>>>(x, gw, gb);
    // ffn1: active CTAs ~ 16 x ceil(1024/256) x 2 = 128 (single wave)
    ffn_mma_kernel<DM, true, 1>
        <<<dim3(DF / BN, TOKENS / BM, 2), 512, SMEM_TOTAL>>>(x, w1, b1, nullptr);
    // ffn2: split-K=2; active CTAs ~ 8 x 4 x 4 = 128 (single wave)
    ffn_mma_kernel<DF / 2, false, 2>
        <<<dim3(DM / BN, TOKENS / BM, 4), 512, SMEM_TOTAL>>>(x, w2, b2, out);
}

// round 9
// speedup vs baseline: 1.4768x; 1.4768x over previous
#include <cuda_runtime.h>
#include <math.h>
#include <stdint.h>

#define TOKENS 8192
#define DM 1024
#define DF 2048
#define NE 8

// ---------------- scratch (device globals: allocation-free, graph-safe) -------------
__device__ int   g_cnt[2];
__device__ int   g_idx[2][TOKENS];
__device__ float g_scale[2][TOKENS];
__device__ float g_h[2][(size_t)TOKENS * DF];

__global__ void reset_kernel() {
    if (threadIdx.x < 2) g_cnt[threadIdx.x] = 0;
}

// One warp per token. Transposed gate weights in smem: sgwT[e][d] -> per-d reads are
// bank = d%32 = lane (conflict-free).
__global__ __launch_bounds__(256) void gate_kernel(const float* __restrict__ x,
                                                   const float* __restrict__ gw,
                                                   const float* __restrict__ gb) {
    __shared__ float sgwT[NE][DM];
    for (int i = threadIdx.x; i < DM * NE; i += 256) {
        int d = i >> 3, e = i & 7;   // gw is [d][e] row-major
        sgwT[e][d] = gw[i];
    }
    __syncthreads();

    const int t    = (int)((blockIdx.x * 256u + threadIdx.x) >> 5);
    const int lane = threadIdx.x & 31;
    if (t >= TOKENS) return;

    const float* xr = x + (size_t)t * DM;
    float acc[NE];
#pragma unroll
    for (int e = 0; e < NE; e++) acc[e] = 0.f;
    for (int d = lane; d < DM; d += 32) {
        const float xv = xr[d];
#pragma unroll
        for (int e = 0; e < NE; e++) acc[e] += xv * sgwT[e][d];
    }
#pragma unroll
    for (int e = 0; e < NE; e++)
#pragma unroll
        for (int o = 16; o > 0; o >>= 1) acc[e] += __shfl_xor_sync(0xffffffffu, acc[e], o);

    if (lane == 0) {
        float p[NE];
        float mx = -1e30f;
#pragma unroll
        for (int e = 0; e < NE; e++) { p[e] = acc[e] + gb[e]; mx = fmaxf(mx, p[e]); }
        float s = 0.f;
#pragma unroll
        for (int e = 0; e < NE; e++) { p[e] = expf(p[e] - mx); s += p[e]; }
        float inv = 1.f / s;
#pragma unroll
        for (int e = 0; e < NE; e++) p[e] *= inv;
        int i1 = 0;
#pragma unroll
        for (int e = 1; e < NE; e++) if (p[e] > p[i1]) i1 = e;
        int i2 = (i1 == 0) ? 1 : 0;
#pragma unroll
        for (int e = 0; e < NE; e++) if (e != i1 && p[e] > p[i2]) i2 = e;
        if (i1 == 0) { int s0 = atomicAdd(&g_cnt[0], 1); g_idx[0][s0] = t; g_scale[0][s0] = p[0]; }
        if (i2 == 1) { int s1 = atomicAdd(&g_cnt[1], 1); g_idx[1][s1] = t; g_scale[1][s1] = p[1]; }
    }
}

// ---------------- tf32 mma.sync GEMM with cp.async pipeline (R6-proven config) -------
__device__ __forceinline__ float tf32r(float x) {
    float y;
    asm("cvt.rna.tf32.f32 %0, %1;" : "=f"(y) : "f"(x));
    return y;
}
__device__ __forceinline__ void mma_tf32(float* d, const uint32_t* a, const uint32_t* b) {
    asm volatile(
        "mma.sync.aligned.m16n8k8.row.col.f32.tf32.tf32.f32 "
        "{%0,%1,%2,%3}, {%4,%5,%6,%7}, {%8,%9}, {%0,%1,%2,%3};"
        : "+f"(d[0]), "+f"(d[1]), "+f"(d[2]), "+f"(d[3])
        : "r"(a[0]), "r"(a[1]), "r"(a[2]), "r"(a[3]), "r"(b[0]), "r"(b[1]));
}
__device__ __forceinline__ uint32_t smem_u32(const void* p) {
    uint32_t a;
    asm("{ .reg .u64 t; cvta.to.shared.u64 t, %1; cvt.u32.u64 %0, t; }" : "=r"(a) : "l"(p));
    return a;
}
#define CP_ASYNC16(dst, src, srcsz) \
    asm volatile("cp.async.cg.shared.global [%0], [%1], 16, %2;" \
                 :: "r"(dst), "l"(src), "r"(srcsz))
#define CP_COMMIT() asm volatile("cp.async.commit_group;" ::: "memory")
#define CP_WAIT1()  asm volatile("cp.async.wait_group 1;" ::: "memory")

// CTA tile 128x128, BK=32, 4 warps as 2(M) x 2(N); warp tile 64x64. 128 threads.
#define BM 128
#define BN 128
#define BK 32
#define AS_STRIDE 36
#define BS_STRIDE (BN + 8)
#define STAGES 3
#define AS_FLOATS (BM * AS_STRIDE)
#define STAGE_FLOATS (AS_FLOATS + BK * BS_STRIDE)
#define STAGE_BYTES (STAGE_FLOATS * 4)
#define SMEM_TOTAL (STAGES * STAGE_BYTES)

template <int KSLICE, bool IS_FFN1, int SPLITK>
__global__ void __launch_bounds__(128, 2) ffn_mma_kernel(const float* __restrict__ x,
                                                         const float* __restrict__ W,
                                                         const float* __restrict__ bias,
                                                         float* __restrict__ outp) {
    const int e     = blockIdx.z / SPLITK;
    const int split = blockIdx.z % SPLITK;
    const int n_act = g_cnt[e];
    const int m0    = blockIdx.y * BM;
    if (m0 >= n_act) return;
    const int NOUT  = IS_FFN1 ? DF : DM;
    const int KTOT  = IS_FFN1 ? DM : DF;
    const int n0    = blockIdx.x * BN;
    const int kbase = split * KSLICE;
    const float* __restrict__ Wq = W + (size_t)e * KTOT * NOUT;

    extern __shared__ float dynsmem[];

    const int tid  = threadIdx.x;
    const int wid  = tid >> 5;
    const int lane = tid & 31;
    const int gid  = lane >> 2;
    const int tig  = lane & 3;
    const int wm0  = (wid >> 1) * 64;   // 0 / 64
    const int wn0  = (wid & 1) * 64;    // 0 / 64

    // A gather: thread t loads full row t (32 floats = 8 float4)
    const int arow = tid;
    const float* aptr;
    uint32_t a_sz;
    {
        int r = m0 + arow;
        bool v = r < n_act;
        int ridx = v ? (IS_FFN1 ? g_idx[e][r] : r) : 0;
        aptr = (IS_FFN1 ? (x + (size_t)ridx * DM) : (g_h[e] + (size_t)ridx * DF)) + kbase;
        a_sz = v ? 16u : 0u;
    }
    // B: thread covers k-row bk (0..31), 8 float4 across 128 cols (4 threads/row)
    const int bk = tid >> 2, bq = tid & 3;
    const float* bptr = Wq + (size_t)(kbase + bk) * NOUT + n0;

    const uint32_t as_dst = smem_u32(dynsmem) + (uint32_t)(arow * AS_STRIDE * 4);
    const uint32_t bs_dst = smem_u32(dynsmem) + (uint32_t)((AS_FLOATS + bk * BS_STRIDE) * 4);

    const int NCHUNK = KSLICE / BK;

    auto issue = [&](int chunk) {
        if (chunk < NCHUNK) {
            const uint32_t sb = (uint32_t)((chunk % STAGES) * STAGE_BYTES);
            const float* ap = aptr + chunk * BK;
            const float* bp = bptr + (size_t)chunk * BK * NOUT;
#pragma unroll
            for (int i = 0; i < 8; i++)
                CP_ASYNC16(as_dst + sb + i * 16, ap + i * 4, a_sz);
#pragma unroll
            for (int j = 0; j < 8; j++) {
                const int colf = (bq + j * 4) * 4;   // float col
                CP_ASYNC16(bs_dst + sb + colf * 4, bp + colf, 16u);
            }
        }
        CP_COMMIT();   // uniform groups: wait_group(1) always pins chunk i
    };

    float c[4][8][4];
#pragma unroll
    for (int mi = 0; mi < 4; mi++)
#pragma unroll
        for (int ni = 0; ni < 8; ni++)
#pragma unroll
            for (int q = 0; q < 4; q++) c[mi][ni][q] = 0.f;

    issue(0);
    issue(1);

    for (int i = 0; i < NCHUNK; i++) {
        CP_WAIT1();
        __syncthreads();
        const float* As = dynsmem + (i % STAGES) * STAGE_FLOATS;
        const float* Bs = As + AS_FLOATS;

#pragma unroll
        for (int ks = 0; ks < 4; ks++) {
            const int kk = ks * 8;
            uint32_t a[4][4], b[8][2];
#pragma unroll
            for (int mi = 0; mi < 4; mi++) {
                const int r = wm0 + mi * 16 + gid;
                a[mi][0] = __float_as_uint(tf32r(As[r * AS_STRIDE + kk + tig]));
                a[mi][1] = __float_as_uint(tf32r(As[(r + 8) * AS_STRIDE + kk + tig]));
                a[mi][2] = __float_as_uint(tf32r(As[r * AS_STRIDE + kk + tig + 4]));
                a[mi][3] = __float_as_uint(tf32r(As[(r + 8) * AS_STRIDE + kk + tig + 4]));
            }
#pragma unroll
            for (int ni = 0; ni < 8; ni++) {
                const int nn = wn0 + ni * 8 + gid;
                b[ni][0] = __float_as_uint(tf32r(Bs[(kk + tig) * BS_STRIDE + nn]));
                b[ni][1] = __float_as_uint(tf32r(Bs[(kk + tig + 4) * BS_STRIDE + nn]));
            }
#pragma unroll
            for (int mi = 0; mi < 4; mi++)
#pragma unroll
                for (int ni = 0; ni < 8; ni++) mma_tf32(c[mi][ni], a[mi], b[ni]);
        }
        __syncthreads();
        issue(i + 2);
    }

    // ---------------- epilogue ----------------
    const float* bb = bias + (size_t)e * NOUT + n0;
    if (IS_FFN1) {
#pragma unroll
        for (int mi = 0; mi < 4; mi++) {
#pragma unroll
            for (int half = 0; half < 2; half++) {
                const int r = m0 + wm0 + mi * 16 + gid + half * 8;
                if (r < n_act) {
                    const float sc = g_scale[e][r];          // fold scale into h
                    float* hrow = g_h[e] + (size_t)r * DF + n0;
#pragma unroll
                    for (int ni = 0; ni < 8; ni++) {
                        const int nn = wn0 + ni * 8 + 2 * tig;
                        float v0 = c[mi][ni][2 * half + 0] + bb[nn];
                        float v1 = c[mi][ni][2 * half + 1] + bb[nn + 1];
                        float2 o;
                        o.x = sc * (0.5f * v0 * (1.f + erff(v0 * 0.70710678118654752f)));
                        o.y = sc * (0.5f * v1 * (1.f + erff(v1 * 0.70710678118654752f)));
                        *(float2*)(hrow + nn) = o;
                    }
                }
            }
        }
    } else {
#pragma unroll
        for (int mi = 0; mi < 4; mi++) {
#pragma unroll
            for (int half = 0; half < 2; half++) {
                const int r = m0 + wm0 + mi * 16 + gid + half * 8;
                if (r < n_act) {
                    const int   tok = g_idx[e][r];
                    const float sc  = g_scale[e][r];
                    float* orow = outp + (size_t)tok * DM + n0;
#pragma unroll
                    for (int ni = 0; ni < 8; ni++) {
                        const int nn = wn0 + ni * 8 + 2 * tig;
                        // h already carries sc; bias needs sc, added by split 0 only
                        float bb0 = (split == 0) ? sc * bb[nn]     : 0.f;
                        float bb1 = (split == 0) ? sc * bb[nn + 1] : 0.f;
                        atomicAdd(orow + nn,     c[mi][ni][2 * half + 0] + bb0);
                        atomicAdd(orow + nn + 1, c[mi][ni][2 * half + 1] + bb1);
                    }
                }
            }
        }
    }
}

extern "C" void kernel_launch(void* const* d_in, const int* in_sizes, int n_in,
                              void* d_out, int out_size) {
    const float* x  = (const float*)d_in[0];
    const float* gw = (const float*)d_in[1];
    const float* gb = (const float*)d_in[2];
    const float* w1 = (const float*)d_in[3];
    const float* b1 = (const float*)d_in[4];
    const float* w2 = (const float*)d_in[5];
    const float* b2 = (const float*)d_in[6];
    float* out = (float*)d_out;

    cudaFuncSetAttribute(ffn_mma_kernel<DM, true, 1>,
                         cudaFuncAttributeMaxDynamicSharedMemorySize, SMEM_TOTAL);
    cudaFuncSetAttribute(ffn_mma_kernel<DF / 2, false, 2>,
                         cudaFuncAttributeMaxDynamicSharedMemorySize, SMEM_TOTAL);

    cudaMemsetAsync(out, 0, (size_t)out_size * sizeof(float), 0);
    reset_kernel<<<1, 32>>>();
    gate_kernel<<<TOKENS / 8, 256>>>(x, gw, gb);
    // ffn1: active CTAs ~ 16x8x2 = 256 -> single wave at 2 CTA/SM
    ffn_mma_kernel<DM, true, 1>
        <<<dim3(DF / BN, TOKENS / BM, 2), 128, SMEM_TOTAL>>>(x, w1, b1, nullptr);
    // ffn2: split-K=2; active CTAs ~ 8x8x4 = 256 -> single wave at 2 CTA/SM
    ffn_mma_kernel<DF / 2, false, 2>
        <<<dim3(DM / BN, TOKENS / BM, 4), 128, SMEM_TOTAL>>>(x, w2, b2, out);
}